// round 6
// baseline (speedup 1.0000x reference)
#include <cuda_runtime.h>
#include <math.h>

#define NB     32
#define NH     32
#define NHKV   8
#define NG     4
#define ND     128
#define NPG    32        // logical pages per sequence
#define PS     128       // slots per page
#define NPAGES 1024
#define SCALE  0.08838834764831845f   // 1/sqrt(128)

// page floats per (page, head): PS*ND = 16384 floats = 4096 float4
#define PAGE_F4 4096

// -------- device scratch (static __device__ arrays: allocation-free) --------
__device__ int   g_inv[NPAGES];                                // phys -> b*NPG+lp
__device__ float g_Pm[NB * NHKV * NG * NPG];                   // partial max
__device__ float g_Pl[NB * NHKV * NG * NPG];                   // partial expsum
__device__ float g_Pacc[(size_t)NB * NHKV * NG * NPG * ND];    // partial P*V (16.8 MB)

// ---------------------------------------------------------------------------
__global__ void inv_kernel(const int* __restrict__ pt) {
    int i = blockIdx.x * blockDim.x + threadIdx.x;
    if (i < NPAGES) g_inv[pt[i]] = i;
}

// ---------------------------------------------------------------------------
// One block per (kv-head, physical page). 256 threads.
// Copies K and V page tiles (input cache -> output cache, with the new token
// substituted), staging through SMEM, and computes the split-softmax partial
// attention for the 4 GQA query heads of this kv-head.
__global__ void __launch_bounds__(256, 3)
fused_kernel(const float* __restrict__ q,
             const float* __restrict__ knew,
             const float* __restrict__ vnew,
             const float* __restrict__ kc,
             const float* __restrict__ vc,
             const int*   __restrict__ pos_,
             const int*   __restrict__ pt,
             float* __restrict__ ok,
             float* __restrict__ ov)
{
    extern __shared__ __align__(16) float smembuf[];
    float (*sk)[ND] = (float (*)[ND])smembuf;                    // [128][128] tile
    float (*qs)[ND] = (float (*)[ND])(smembuf + PS * ND);        // [4][128] query
    float (*sp)[PS] = (float (*)[PS])(smembuf + PS * ND + NG * ND); // [4][128] scores/probs
    float* sml = smembuf + PS * ND + NG * ND + NG * PS;          // m[4], l[4]

    const int h  = blockIdx.x;        // kv head
    const int pp = blockIdx.y;        // physical page
    const int t  = threadIdx.x;

    const int owner = g_inv[pp];
    const int b  = owner >> 5;        // /NPG
    const int lp = owner & 31;        // %NPG
    const int pos = pos_[b];
    const int upd_page = pt[b * NPG + (pos >> 7)];
    const int upd_slot = pos & 127;
    const bool has_upd = (pp == upd_page);

    const bool do_attn = (lp << 7) <= pos;                       // block-uniform
    const int nvalid = do_attn ? min(PS, pos - (lp << 7) + 1) : 0;

    // load 4 query heads (512 contiguous floats) -> qs
    if (do_attn) {
        const float2* qb = (const float2*)(q + ((size_t)b * NH + h * NG) * ND);
        ((float2*)&qs[0][0])[t] = qb[t];
    }

    const size_t pageoff = ((size_t)pp * NHKV + h) * (PS * ND);

    // ---------------- K: stage + copy (with token substitution) ----------------
    {
        const float4* src = (const float4*)(kc + pageoff);
        float4*       dst = (float4*)(ok + pageoff);
        const float4* kn  = (const float4*)(knew + ((size_t)b * NHKV + h) * ND);
        float4*       ssk = (float4*)&sk[0][0];
#pragma unroll
        for (int i = 0; i < 16; i++) {
            int idx = t + i * 256;                // float4 index, 32 per row
            float4 v = __ldcs(&src[idx]);
            if (has_upd && (idx >> 5) == upd_slot) v = kn[idx & 31];
            ssk[idx] = v;
            __stcs(&dst[idx], v);
        }
    }
    __syncthreads();

    const int w = t >> 5, lane = t & 31;

    if (do_attn) {
        // -------- QK: warp w handles rows w, w+8, ... (LDS.128, conflict-free)
        float4 q0 = ((float4*)&qs[0][0])[lane];
        float4 q1 = ((float4*)&qs[1][0])[lane];
        float4 q2 = ((float4*)&qs[2][0])[lane];
        float4 q3 = ((float4*)&qs[3][0])[lane];
        for (int r = w; r < PS; r += 8) {
            float4 kv = ((float4*)&sk[r][0])[lane];
            float s0 = kv.x*q0.x + kv.y*q0.y + kv.z*q0.z + kv.w*q0.w;
            float s1 = kv.x*q1.x + kv.y*q1.y + kv.z*q1.z + kv.w*q1.w;
            float s2 = kv.x*q2.x + kv.y*q2.y + kv.z*q2.z + kv.w*q2.w;
            float s3 = kv.x*q3.x + kv.y*q3.y + kv.z*q3.z + kv.w*q3.w;
#pragma unroll
            for (int off = 16; off; off >>= 1) {
                s0 += __shfl_xor_sync(0xffffffffu, s0, off);
                s1 += __shfl_xor_sync(0xffffffffu, s1, off);
                s2 += __shfl_xor_sync(0xffffffffu, s2, off);
                s3 += __shfl_xor_sync(0xffffffffu, s3, off);
            }
            if (lane == 0) {
                bool valid = r < nvalid;
                sp[0][r] = valid ? s0 * SCALE : -INFINITY;
                sp[1][r] = valid ? s1 * SCALE : -INFINITY;
                sp[2][r] = valid ? s2 * SCALE : -INFINITY;
                sp[3][r] = valid ? s3 * SCALE : -INFINITY;
            }
        }
        __syncthreads();

        // -------- partial softmax: warp g reduces sp[g][0..127]
        if (w < NG) {
            float4 v = ((float4*)&sp[w][0])[lane];
            float m = fmaxf(fmaxf(v.x, v.y), fmaxf(v.z, v.w));
#pragma unroll
            for (int off = 16; off; off >>= 1)
                m = fmaxf(m, __shfl_xor_sync(0xffffffffu, m, off));
            float4 e;
            e.x = __expf(v.x - m); e.y = __expf(v.y - m);
            e.z = __expf(v.z - m); e.w = __expf(v.w - m);
            float l = e.x + e.y + e.z + e.w;
#pragma unroll
            for (int off = 16; off; off >>= 1)
                l += __shfl_xor_sync(0xffffffffu, l, off);
            ((float4*)&sp[w][0])[lane] = e;
            if (lane == 0) { sml[w] = m; sml[4 + w] = l; }
        }
        __syncthreads();
    }

    // ---------------- V: stage + copy (with token substitution) ----------------
    {
        const float4* src = (const float4*)(vc + pageoff);
        float4*       dst = (float4*)(ov + pageoff);
        const float4* vn  = (const float4*)(vnew + ((size_t)b * NHKV + h) * ND);
        float4*       ssk = (float4*)&sk[0][0];
#pragma unroll
        for (int i = 0; i < 16; i++) {
            int idx = t + i * 256;
            float4 v = __ldcs(&src[idx]);
            if (has_upd && (idx >> 5) == upd_slot) v = vn[idx & 31];
            ssk[idx] = v;
            __stcs(&dst[idx], v);
        }
    }
    __syncthreads();

    if (do_attn) {
        // -------- P*V: thread t -> (qh=t>>7, d=t&127) and (qh+2, d); shared V read
        const int d  = t & 127;
        const int qa = t >> 7;                   // 0 or 1
        float a0 = 0.f, a1 = 0.f;
#pragma unroll 4
        for (int r = 0; r < nvalid; r++) {
            float vv = sk[r][d];
            a0 = fmaf(sp[qa][r],     vv, a0);
            a1 = fmaf(sp[qa + 2][r], vv, a1);
        }
        const int u = ((b * NHKV) + h) * NG;     // == b*32 + h*4
        g_Pacc[(size_t)((u + qa)     * NPG + lp) * ND + d] = a0;
        g_Pacc[(size_t)((u + qa + 2) * NPG + lp) * ND + d] = a1;
        if (t < NG) {
            int id = (u + t) * NPG + lp;
            g_Pm[id] = sml[t];
            g_Pl[id] = sml[4 + t];
        }
    }
}

// ---------------------------------------------------------------------------
// Combine split-softmax partials: one block per (b, global q-head), 128 threads.
__global__ void reduce_kernel(const int* __restrict__ pos_, float* __restrict__ out)
{
    const int u = blockIdx.x;                  // b*32 + (hkv*4+g)
    const int b = u >> 5;
    const int d = threadIdx.x;
    const int npg = (pos_[b] >> 7) + 1;

    float M = -INFINITY, L = 0.f, O = 0.f;
    for (int lp = 0; lp < npg; lp++) {
        float m  = g_Pm[u * NPG + lp];
        float l  = g_Pl[u * NPG + lp];
        float Mn = fmaxf(M, m);
        float c0 = __expf(M - Mn);
        float c1 = __expf(m - Mn);
        O = O * c0 + g_Pacc[(size_t)(u * NPG + lp) * ND + d] * c1;
        L = L * c0 + l * c1;
        M = Mn;
    }
    out[(size_t)u * ND + d] = O / L;
}

// ---------------------------------------------------------------------------
extern "C" void kernel_launch(void* const* d_in, const int* in_sizes, int n_in,
                              void* d_out, int out_size)
{
    const float* q   = (const float*)d_in[0];
    const float* kn  = (const float*)d_in[1];
    const float* vn  = (const float*)d_in[2];
    const float* kc  = (const float*)d_in[3];
    const float* vc  = (const float*)d_in[4];
    const int*   pos = (const int*)d_in[5];
    const int*   pt  = (const int*)d_in[6];

    float* out_attn = (float*)d_out;
    float* out_k    = out_attn + (size_t)NB * NH * ND;             // +131072
    float* out_v    = out_k + (size_t)NPAGES * NHKV * PS * ND;     // +134217728

    const int smem = (PS * ND + NG * ND + NG * PS + 8) * sizeof(float); // 69664 B
    cudaFuncSetAttribute(fused_kernel, cudaFuncAttributeMaxDynamicSharedMemorySize, smem);

    inv_kernel<<<1, NPAGES>>>(pt);
    fused_kernel<<<dim3(NHKV, NPAGES), 256, smem>>>(q, kn, vn, kc, vc, pos, pt,
                                                    out_k, out_v);
    reduce_kernel<<<NB * NH, ND>>>(pos, out_attn);
}

// round 8
// speedup vs baseline: 1.4752x; 1.4752x over previous
#include <cuda_runtime.h>
#include <cstdint>
#include <math.h>

#define NB     32
#define NH     32
#define NHKV   8
#define NG     4
#define ND     128
#define NPG    32
#define PS     128
#define NPAGES 1024
#define NUNITS (NPAGES * NHKV * 2)     // 16384 half-page units
#define NHP    64                      // half-page partials per sequence
#define TILE_F 8192                    // floats per half tile (64 x 128)
#define TILE_B 32768u                  // bytes per half tile
#define SCALE  0.08838834764831845f    // 1/sqrt(128)

// -------- device scratch (static: allocation-free) --------
__device__ int   g_inv[NPAGES];                                 // phys -> b*NPG+lp
__device__ float g_Pm[NB * NH * NHP];                           // partial max
__device__ float g_Pl[NB * NH * NHP];                           // partial expsum
__device__ float g_Pacc[(size_t)NB * NH * NHP * ND];            // partial P*V (33.5 MB)

// ---------------- PTX helpers ----------------
__device__ __forceinline__ void mbar_init(uint32_t a, int cnt) {
    asm volatile("mbarrier.init.shared.b64 [%0], %1;" :: "r"(a), "r"(cnt) : "memory");
}
__device__ __forceinline__ void mbar_expect(uint32_t a, uint32_t bytes) {
    asm volatile("mbarrier.arrive.expect_tx.shared.b64 _, [%0], %1;"
                 :: "r"(a), "r"(bytes) : "memory");
}
__device__ __forceinline__ void mbar_wait(uint32_t a, int parity) {
    asm volatile(
        "{\n\t.reg .pred P;\n\t"
        "W%=:\n\t"
        "mbarrier.try_wait.parity.acquire.cta.shared::cta.b64 P, [%0], %1, 0x989680;\n\t"
        "@P bra.uni D%=;\n\t"
        "bra.uni W%=;\n\t"
        "D%=:\n\t}"
        :: "r"(a), "r"(parity) : "memory");
}
__device__ __forceinline__ void bulk_ld(uint32_t dst, const void* src, uint32_t bytes, uint32_t mbar) {
    asm volatile("cp.async.bulk.shared::cta.global.mbarrier::complete_tx::bytes [%0], [%1], %2, [%3];"
                 :: "r"(dst), "l"(src), "r"(bytes), "r"(mbar) : "memory");
}
__device__ __forceinline__ void bulk_st(void* dst, uint32_t src, uint32_t bytes) {
    asm volatile("cp.async.bulk.global.shared::cta.bulk_group [%0], [%1], %2;"
                 :: "l"(dst), "r"(src), "r"(bytes) : "memory");
}

// ---------------------------------------------------------------------------
__global__ void inv_kernel(const int* __restrict__ pt) {
    int i = threadIdx.x;
    if (i < NPAGES) g_inv[pt[i]] = i;
}

// ---------------------------------------------------------------------------
// Persistent fused copy+attend. One block per SM, 512 threads.
// SMEM: 3-stage ring of (K 32KB + V 32KB) tiles + qs + sp + mbarriers.
__global__ void __launch_bounds__(512, 1)
fused_kernel(const float* __restrict__ q,
             const float* __restrict__ knew,
             const float* __restrict__ vnew,
             const float* __restrict__ kc,
             const float* __restrict__ vc,
             const int*   __restrict__ pos_,
             const int*   __restrict__ pt,
             float* __restrict__ ok,
             float* __restrict__ ov)
{
    extern __shared__ __align__(128) float smf[];
    // layout: K tiles [3][8192] | V tiles [3][8192] | qs[512] | sp[4][64] | mbars
    float* qs = smf + 6 * TILE_F;
    float* sp = qs + 512;
    const uint32_t smbase = (uint32_t)__cvta_generic_to_shared(smf);
    const uint32_t mb0 = (uint32_t)__cvta_generic_to_shared(sp + 256);

    const int t = threadIdx.x;
    const int w = t >> 5, lane = t & 31;
    const int grid = gridDim.x;

    if (t == 0) {
        mbar_init(mb0,      1);
        mbar_init(mb0 + 8,  1);
        mbar_init(mb0 + 16, 1);
    }
    __syncthreads();

    int u = blockIdx.x;
    // prologue: prefetch unit u into stage 0  (unit base = u * 8192 floats)
    if (t == 0 && u < NUNITS) {
        mbar_expect(mb0, 2 * TILE_B);
        bulk_ld(smbase,                kc + (size_t)u * TILE_F, TILE_B, mb0);
        bulk_ld(smbase + 3 * TILE_B,   vc + (size_t)u * TILE_F, TILE_B, mb0);
    }

    int it = 0;
    for (; u < NUNITS; u += grid, ++it) {
        const int s = it % 3;
        float* kb = smf + s * TILE_F;
        float* vb = smf + (3 + s) * TILE_F;

        __syncthreads();   // prev iter's reads of all buffers done

        // ---- prefetch next unit (stage s+1; its store group is >=2 old) ----
        const int un = u + grid;
        if (t == 0 && un < NUNITS) {
            const int sn = (s + 1) % 3;
            asm volatile("cp.async.bulk.wait_group.read 1;" ::: "memory");
            mbar_expect(mb0 + 8 * sn, 2 * TILE_B);
            bulk_ld(smbase + sn * TILE_B,       kc + (size_t)un * TILE_F, TILE_B, mb0 + 8 * sn);
            bulk_ld(smbase + (3 + sn) * TILE_B, vc + (size_t)un * TILE_F, TILE_B, mb0 + 8 * sn);
        }

        // ---- unit metadata ----
        const int pp = u >> 4, h = (u >> 1) & 7, hf = u & 1;
        const int owner = g_inv[pp];
        const int b = owner >> 5, lp = owner & 31;
        const int pos = pos_[b];
        const int startrow = lp * PS + hf * 64;
        const bool do_attn = startrow <= pos;
        const int nvalid = min(64, pos - startrow + 1);
        const int slot = pos & 127;
        const bool has_upd = (pp == pt[b * NPG + (pos >> 7)]) && ((slot >> 6) == hf);
        const size_t base = (size_t)u * TILE_F;     // floats into cache arrays

        // ---- wait current tiles ----
        mbar_wait(mb0 + 8 * s, (it / 3) & 1);

        // q load (512 floats) + token patch (rows in SMEM, pre-store & pre-compute)
        if (do_attn) qs[t] = q[((size_t)b * NH + h * NG) * ND + t];
        if (has_upd) {
            const int r = slot & 63;
            if (t < 32)
                ((float4*)(kb + r * ND))[t] =
                    ((const float4*)(knew + ((size_t)b * NHKV + h) * ND))[t];
            else if (t < 64)
                ((float4*)(vb + r * ND))[t - 32] =
                    ((const float4*)(vnew + ((size_t)b * NHKV + h) * ND))[t - 32];
        }
        __syncthreads();

        // ---- async bulk store of (patched) tiles ----
        if (t == 0) {
            asm volatile("fence.proxy.async.shared::cta;" ::: "memory");
            bulk_st(ok + base, smbase + s * TILE_B,       TILE_B);
            bulk_st(ov + base, smbase + (3 + s) * TILE_B, TILE_B);
            asm volatile("cp.async.bulk.commit_group;" ::: "memory");
        }

        if (do_attn) {
            // ---- QK: warp w rows {w, w+16, w+32, w+48}; float4 + shuffle ----
            const float4 q0 = ((const float4*)qs)[lane];
            const float4 q1 = ((const float4*)qs)[32 + lane];
            const float4 q2 = ((const float4*)qs)[64 + lane];
            const float4 q3 = ((const float4*)qs)[96 + lane];
            for (int r = w; r < 64; r += 16) {
                float4 kv = ((const float4*)(kb + r * ND))[lane];
                float s0 = kv.x*q0.x + kv.y*q0.y + kv.z*q0.z + kv.w*q0.w;
                float s1 = kv.x*q1.x + kv.y*q1.y + kv.z*q1.z + kv.w*q1.w;
                float s2 = kv.x*q2.x + kv.y*q2.y + kv.z*q2.z + kv.w*q2.w;
                float s3 = kv.x*q3.x + kv.y*q3.y + kv.z*q3.z + kv.w*q3.w;
#pragma unroll
                for (int off = 16; off; off >>= 1) {
                    s0 += __shfl_xor_sync(0xffffffffu, s0, off);
                    s1 += __shfl_xor_sync(0xffffffffu, s1, off);
                    s2 += __shfl_xor_sync(0xffffffffu, s2, off);
                    s3 += __shfl_xor_sync(0xffffffffu, s3, off);
                }
                if (lane == 0) {
                    bool val = r < nvalid;
                    sp[r]       = val ? s0 * SCALE : -INFINITY;
                    sp[64 + r]  = val ? s1 * SCALE : -INFINITY;
                    sp[128 + r] = val ? s2 * SCALE : -INFINITY;
                    sp[192 + r] = val ? s3 * SCALE : -INFINITY;
                }
            }
            __syncthreads();

            // ---- partial softmax: warp g reduces its 64 scores ----
            if (w < NG) {
                float2 v2 = ((const float2*)(sp + w * 64))[lane];
                float m = fmaxf(v2.x, v2.y);
#pragma unroll
                for (int off = 16; off; off >>= 1)
                    m = fmaxf(m, __shfl_xor_sync(0xffffffffu, m, off));
                float ex = __expf(v2.x - m), ey = __expf(v2.y - m);
                float l = ex + ey;
#pragma unroll
                for (int off = 16; off; off >>= 1)
                    l += __shfl_xor_sync(0xffffffffu, l, off);
                ((float2*)(sp + w * 64))[lane] = make_float2(ex, ey);
                if (lane == 0) {
                    int id = (b * NH + h * NG + w) * NHP + lp * 2 + hf;
                    g_Pm[id] = m;
                    g_Pl[id] = l;
                }
            }
            __syncthreads();

            // ---- P*V: thread t -> (qh = t>>7, d = t&127), dual accumulators ----
            const int qh = t >> 7, d = t & 127;
            const float* spq = sp + qh * 64;
            float a0 = 0.f, a1 = 0.f;
            int r = 0;
            for (; r + 1 < nvalid; r += 2) {
                a0 = fmaf(spq[r],     vb[r * ND + d],       a0);
                a1 = fmaf(spq[r + 1], vb[(r + 1) * ND + d], a1);
            }
            if (r < nvalid) a0 = fmaf(spq[r], vb[r * ND + d], a0);
            g_Pacc[(size_t)((b * NH + h * NG + qh) * NHP + lp * 2 + hf) * ND + d] = a0 + a1;
        }
    }

    // drain outstanding bulk stores before SMEM is retired
    if (t == 0) asm volatile("cp.async.bulk.wait_group 0;" ::: "memory");
}

// ---------------------------------------------------------------------------
// Combine split-softmax partials: one block per (b, q-head), 128 threads.
__global__ void reduce_kernel(const int* __restrict__ pos_, float* __restrict__ out)
{
    const int uu = blockIdx.x;          // b*32 + h*4 + g
    const int b = uu >> 5;
    const int d = threadIdx.x;
    const int nhp = (pos_[b] >> 6) + 1;

    float M = -INFINITY, L = 0.f, O = 0.f;
    for (int hp = 0; hp < nhp; hp++) {
        float m  = g_Pm[uu * NHP + hp];
        float l  = g_Pl[uu * NHP + hp];
        float Mn = fmaxf(M, m);
        float c0 = __expf(M - Mn);
        float c1 = __expf(m - Mn);
        O = O * c0 + g_Pacc[(size_t)(uu * NHP + hp) * ND + d] * c1;
        L = L * c0 + l * c1;
        M = Mn;
    }
    out[(size_t)uu * ND + d] = O / L;
}

// ---------------------------------------------------------------------------
extern "C" void kernel_launch(void* const* d_in, const int* in_sizes, int n_in,
                              void* d_out, int out_size)
{
    const float* q   = (const float*)d_in[0];
    const float* kn  = (const float*)d_in[1];
    const float* vn  = (const float*)d_in[2];
    const float* kc  = (const float*)d_in[3];
    const float* vc  = (const float*)d_in[4];
    const int*   pos = (const int*)d_in[5];
    const int*   pt  = (const int*)d_in[6];

    float* out_attn = (float*)d_out;
    float* out_k    = out_attn + (size_t)NB * NH * ND;             // +131072
    float* out_v    = out_k + (size_t)NPAGES * NHKV * PS * ND;     // +134217728

    int nsm = 148;
    if (cudaDeviceGetAttribute(&nsm, cudaDevAttrMultiProcessorCount, 0) != cudaSuccess || nsm <= 0)
        nsm = 148;

    // 6 tiles * 32KB + qs 2KB + sp 1KB + mbars
    const int smem = (6 * TILE_F + 512 + 256 + 16) * (int)sizeof(float);   // 199744 B
    cudaFuncSetAttribute(fused_kernel, cudaFuncAttributeMaxDynamicSharedMemorySize, smem);

    inv_kernel<<<1, NPAGES>>>(pt);
    fused_kernel<<<nsm, 512, smem>>>(q, kn, vn, kc, vc, pos, pt, out_k, out_v);
    reduce_kernel<<<NB * NH, ND>>>(pos, out_attn);
}